// round 1
// baseline (speedup 1.0000x reference)
#include <cuda_runtime.h>
#include <math.h>

// Problem constants: B=2, T=2048, C=1024, H=16, hd=64
constexpr int kT  = 2048;
constexpr int kC  = 1024;
constexpr int kH  = 16;
constexpr int kHD = 64;
constexpr int kB  = 2;
constexpr int kM  = kB * kT;      // 4096 rows for both GEMMs

// Scratch (allocation-free rule: __device__ globals)
__device__ float g_q[kB * kH * kT * kHD];     // Q in [B,H,T,hd]   (16 MB)
__device__ float g_yatt[kB * kT * kC];        // attention out, [B,T,C] (16 MB)

// ---------------------------------------------------------------------------
// QKV GEMM: [4096,1024] x [1024,3072] + bias, epilogue scatters
//   q -> g_q[B,H,T,hd], k -> kout, v -> vout  (both [B,H,T,hd])
// 128x128 tile, BK=8, 256 threads, 8x8 per thread.
// ---------------------------------------------------------------------------
__global__ void __launch_bounds__(256) qkv_gemm_kernel(
    const float* __restrict__ A, const float* __restrict__ W,
    const float* __restrict__ bias,
    float* __restrict__ kout, float* __restrict__ vout)
{
    constexpr int K = kC;        // 1024
    constexpr int N = 3 * kC;    // 3072
    __shared__ float As[8][128];
    __shared__ float Bs[8][128];

    const int m0 = blockIdx.y * 128;
    const int n0 = blockIdx.x * 128;
    const int tid = threadIdx.x;
    const int tx = tid & 15, ty = tid >> 4;

    float acc[8][8];
#pragma unroll
    for (int i = 0; i < 8; i++)
#pragma unroll
        for (int j = 0; j < 8; j++) acc[i][j] = 0.f;

    const int arow = tid >> 1, akp = (tid & 1) * 4;
    const int bkk  = tid >> 5, bnp = (tid & 31) * 4;

    for (int k0 = 0; k0 < K; k0 += 8) {
        float4 a4 = *reinterpret_cast<const float4*>(A + (size_t)(m0 + arow) * K + k0 + akp);
        As[akp + 0][arow] = a4.x;
        As[akp + 1][arow] = a4.y;
        As[akp + 2][arow] = a4.z;
        As[akp + 3][arow] = a4.w;
        *reinterpret_cast<float4*>(&Bs[bkk][bnp]) =
            *reinterpret_cast<const float4*>(W + (size_t)(k0 + bkk) * N + n0 + bnp);
        __syncthreads();
#pragma unroll
        for (int kk = 0; kk < 8; kk++) {
            float a[8], b[8];
            *reinterpret_cast<float4*>(a)     = *reinterpret_cast<float4*>(&As[kk][ty * 4]);
            *reinterpret_cast<float4*>(a + 4) = *reinterpret_cast<float4*>(&As[kk][64 + ty * 4]);
            *reinterpret_cast<float4*>(b)     = *reinterpret_cast<float4*>(&Bs[kk][tx * 4]);
            *reinterpret_cast<float4*>(b + 4) = *reinterpret_cast<float4*>(&Bs[kk][64 + tx * 4]);
#pragma unroll
            for (int i = 0; i < 8; i++)
#pragma unroll
                for (int j = 0; j < 8; j++) acc[i][j] = fmaf(a[i], b[j], acc[i][j]);
        }
        __syncthreads();
    }

#pragma unroll
    for (int i = 0; i < 8; i++) {
        int m = m0 + (i < 4 ? ty * 4 + i : 64 + ty * 4 + (i - 4));
        int bidx = m >> 11;          // / 2048
        int t    = m & 2047;
#pragma unroll
        for (int j = 0; j < 8; j++) {
            int n = n0 + (j < 4 ? tx * 4 + j : 64 + tx * 4 + (j - 4));
            float v = acc[i][j] + bias[n];
            int s = n >> 10;         // 0:q 1:k 2:v
            int c = n & 1023;
            int h = c >> 6, d = c & 63;
            int idx = ((bidx * kH + h) * kT + t) * kHD + d;
            if (s == 0)      g_q[idx]  = v;
            else if (s == 1) kout[idx] = v;
            else             vout[idx] = v;
        }
    }
}

// ---------------------------------------------------------------------------
// Flash attention (fp32, causal). One CTA per (q-tile of 64, head, batch).
// BR=64, BC=32. 256 threads: 16 row-groups x 16 col-groups.
// ---------------------------------------------------------------------------
__global__ void __launch_bounds__(256) flash_kernel(
    const float* __restrict__ Kg, const float* __restrict__ Vg)
{
    __shared__ float Qs[64][68];   // padded: rows differing by 4 -> different banks
    __shared__ float Ks[64][33];   // transposed [d][c], pad 33 -> conflict-free
    __shared__ float Vs[32][64];
    __shared__ float Ss[64][33];
    __shared__ float m_s[64], l_s[64], alpha_s[64];

    const int tid = threadIdx.x;
    const int qi = blockIdx.x, h = blockIdx.y, b = blockIdx.z;
    const int qbase = qi * 64;
    const size_t head_off = (size_t)(b * kH + h) * kT * kHD;
    const float* Qp = g_q + head_off;
    const float* Kp = Kg + head_off;
    const float* Vp = Vg + head_off;

    // Load Q tile: 64x64 floats = 1024 float4, 4 per thread
#pragma unroll
    for (int it = 0; it < 4; it++) {
        int idx = tid + it * 256;
        int r = idx >> 4;
        int dp = (idx & 15) * 4;
        float4 q4 = *reinterpret_cast<const float4*>(Qp + (size_t)(qbase + r) * kHD + dp);
        Qs[r][dp + 0] = q4.x; Qs[r][dp + 1] = q4.y;
        Qs[r][dp + 2] = q4.z; Qs[r][dp + 3] = q4.w;
    }
    if (tid < 64) { m_s[tid] = -INFINITY; l_s[tid] = 0.f; }

    const int rg = tid >> 4;     // 0..15
    const int cg = tid & 15;     // 0..15
    const int r0 = rg * 4;
    const int sc0 = cg * 2;      // S cols
    const int d0 = cg * 4;       // O dims

    float O[4][4];
#pragma unroll
    for (int i = 0; i < 4; i++)
#pragma unroll
        for (int j = 0; j < 4; j++) O[i][j] = 0.f;

    const float scale = 0.125f;  // 1/sqrt(64)
    const int ntiles = 2 * qi + 2;

    for (int jt = 0; jt < ntiles; jt++) {
        __syncthreads();   // also covers initial Q load / m_s init
        // Load K (transposed into smem) and V tiles: 32x64 each
#pragma unroll
        for (int it = 0; it < 2; it++) {
            int idx = tid + it * 256;       // 0..511
            int c = idx >> 4;               // 0..31
            int dp = (idx & 15) * 4;
            float4 k4 = *reinterpret_cast<const float4*>(Kp + (size_t)(jt * 32 + c) * kHD + dp);
            Ks[dp + 0][c] = k4.x; Ks[dp + 1][c] = k4.y;
            Ks[dp + 2][c] = k4.z; Ks[dp + 3][c] = k4.w;
            float4 v4 = *reinterpret_cast<const float4*>(Vp + (size_t)(jt * 32 + c) * kHD + dp);
            *reinterpret_cast<float4*>(&Vs[c][dp]) = v4;
        }
        __syncthreads();

        // S = scale * Q K^T  (4 rows x 2 cols per thread)
        float s00 = 0.f, s01 = 0.f, s10 = 0.f, s11 = 0.f;
        float s20 = 0.f, s21 = 0.f, s30 = 0.f, s31 = 0.f;
#pragma unroll
        for (int d = 0; d < 64; d++) {
            float kv0 = Ks[d][sc0], kv1 = Ks[d][sc0 + 1];
            float q0 = Qs[r0 + 0][d], q1 = Qs[r0 + 1][d];
            float q2 = Qs[r0 + 2][d], q3 = Qs[r0 + 3][d];
            s00 = fmaf(q0, kv0, s00); s01 = fmaf(q0, kv1, s01);
            s10 = fmaf(q1, kv0, s10); s11 = fmaf(q1, kv1, s11);
            s20 = fmaf(q2, kv0, s20); s21 = fmaf(q2, kv1, s21);
            s30 = fmaf(q3, kv0, s30); s31 = fmaf(q3, kv1, s31);
        }
        {
            float sv[4][2] = {{s00, s01}, {s10, s11}, {s20, s21}, {s30, s31}};
            const bool maskTile = (jt * 32 + 31 > qbase);
#pragma unroll
            for (int i = 0; i < 4; i++)
#pragma unroll
                for (int jj = 0; jj < 2; jj++) {
                    float val = sv[i][jj] * scale;
                    if (maskTile && (jt * 32 + sc0 + jj > qbase + r0 + i)) val = -INFINITY;
                    Ss[r0 + i][sc0 + jj] = val;
                }
        }
        __syncthreads();

        // Online softmax: one thread per row
        if (tid < 64) {
            int r = tid;
            float mo = m_s[r];
            float mx = mo;
#pragma unroll
            for (int c = 0; c < 32; c++) mx = fmaxf(mx, Ss[r][c]);
            float alpha = __expf(mo - mx);
            float sum = 0.f;
#pragma unroll
            for (int c = 0; c < 32; c++) {
                float p = __expf(Ss[r][c] - mx);
                Ss[r][c] = p;
                sum += p;
            }
            l_s[r] = l_s[r] * alpha + sum;
            m_s[r] = mx;
            alpha_s[r] = alpha;
        }
        __syncthreads();

        // Rescale O and accumulate P @ V (4 rows x 4 dims per thread)
#pragma unroll
        for (int i = 0; i < 4; i++) {
            float a = alpha_s[r0 + i];
#pragma unroll
            for (int jj = 0; jj < 4; jj++) O[i][jj] *= a;
        }
#pragma unroll
        for (int k = 0; k < 32; k++) {
            float4 v4 = *reinterpret_cast<float4*>(&Vs[k][d0]);
            float p0 = Ss[r0 + 0][k], p1 = Ss[r0 + 1][k];
            float p2 = Ss[r0 + 2][k], p3 = Ss[r0 + 3][k];
            O[0][0] = fmaf(p0, v4.x, O[0][0]); O[0][1] = fmaf(p0, v4.y, O[0][1]);
            O[0][2] = fmaf(p0, v4.z, O[0][2]); O[0][3] = fmaf(p0, v4.w, O[0][3]);
            O[1][0] = fmaf(p1, v4.x, O[1][0]); O[1][1] = fmaf(p1, v4.y, O[1][1]);
            O[1][2] = fmaf(p1, v4.z, O[1][2]); O[1][3] = fmaf(p1, v4.w, O[1][3]);
            O[2][0] = fmaf(p2, v4.x, O[2][0]); O[2][1] = fmaf(p2, v4.y, O[2][1]);
            O[2][2] = fmaf(p2, v4.z, O[2][2]); O[2][3] = fmaf(p2, v4.w, O[2][3]);
            O[3][0] = fmaf(p3, v4.x, O[3][0]); O[3][1] = fmaf(p3, v4.y, O[3][1]);
            O[3][2] = fmaf(p3, v4.z, O[3][2]); O[3][3] = fmaf(p3, v4.w, O[3][3]);
        }
    }
    __syncthreads();

    // Write normalized output to g_yatt in [B,T,C] layout (head h occupies cols h*64..)
#pragma unroll
    for (int i = 0; i < 4; i++) {
        float inv = 1.f / l_s[r0 + i];
        int t = qbase + r0 + i;
        float* yp = g_yatt + (size_t)(b * kT + t) * kC + h * kHD + d0;
        yp[0] = O[i][0] * inv;
        yp[1] = O[i][1] * inv;
        yp[2] = O[i][2] * inv;
        yp[3] = O[i][3] * inv;
    }
}

// ---------------------------------------------------------------------------
// Output projection: [4096,1024] x [1024,1024] + bias -> y
// ---------------------------------------------------------------------------
__global__ void __launch_bounds__(256) proj_gemm_kernel(
    const float* __restrict__ W, const float* __restrict__ bias,
    float* __restrict__ out)
{
    constexpr int K = kC;   // 1024
    constexpr int N = kC;   // 1024
    __shared__ float As[8][128];
    __shared__ float Bs[8][128];

    const float* A = g_yatt;
    const int m0 = blockIdx.y * 128;
    const int n0 = blockIdx.x * 128;
    const int tid = threadIdx.x;
    const int tx = tid & 15, ty = tid >> 4;

    float acc[8][8];
#pragma unroll
    for (int i = 0; i < 8; i++)
#pragma unroll
        for (int j = 0; j < 8; j++) acc[i][j] = 0.f;

    const int arow = tid >> 1, akp = (tid & 1) * 4;
    const int bkk  = tid >> 5, bnp = (tid & 31) * 4;

    for (int k0 = 0; k0 < K; k0 += 8) {
        float4 a4 = *reinterpret_cast<const float4*>(A + (size_t)(m0 + arow) * K + k0 + akp);
        As[akp + 0][arow] = a4.x;
        As[akp + 1][arow] = a4.y;
        As[akp + 2][arow] = a4.z;
        As[akp + 3][arow] = a4.w;
        *reinterpret_cast<float4*>(&Bs[bkk][bnp]) =
            *reinterpret_cast<const float4*>(W + (size_t)(k0 + bkk) * N + n0 + bnp);
        __syncthreads();
#pragma unroll
        for (int kk = 0; kk < 8; kk++) {
            float a[8], b[8];
            *reinterpret_cast<float4*>(a)     = *reinterpret_cast<float4*>(&As[kk][ty * 4]);
            *reinterpret_cast<float4*>(a + 4) = *reinterpret_cast<float4*>(&As[kk][64 + ty * 4]);
            *reinterpret_cast<float4*>(b)     = *reinterpret_cast<float4*>(&Bs[kk][tx * 4]);
            *reinterpret_cast<float4*>(b + 4) = *reinterpret_cast<float4*>(&Bs[kk][64 + tx * 4]);
#pragma unroll
            for (int i = 0; i < 8; i++)
#pragma unroll
                for (int j = 0; j < 8; j++) acc[i][j] = fmaf(a[i], b[j], acc[i][j]);
        }
        __syncthreads();
    }

#pragma unroll
    for (int i = 0; i < 8; i++) {
        int m = m0 + (i < 4 ? ty * 4 + i : 64 + ty * 4 + (i - 4));
#pragma unroll
        for (int j = 0; j < 8; j++) {
            int n = n0 + (j < 4 ? tx * 4 + j : 64 + tx * 4 + (j - 4));
            out[(size_t)m * N + n] = acc[i][j] + bias[n];
        }
    }
}

// ---------------------------------------------------------------------------
// Launch: qkv -> flash -> proj, sequential on default stream (capturable).
// Output layout: [ y (B*T*C) | k (B*H*T*hd) | v (B*H*T*hd) ]
// ---------------------------------------------------------------------------
extern "C" void kernel_launch(void* const* d_in, const int* in_sizes, int n_in,
                              void* d_out, int out_size)
{
    const float* x      = (const float*)d_in[0];
    const float* W_attn = (const float*)d_in[1];
    const float* b_attn = (const float*)d_in[2];
    const float* W_proj = (const float*)d_in[3];
    const float* b_proj = (const float*)d_in[4];

    float* y = (float*)d_out;
    const int seg = out_size / 3;       // 4,194,304 each
    float* kout = y + seg;
    float* vout = y + 2 * seg;

    // QKV: M=4096, N=3072 -> grid (24, 32)
    qkv_gemm_kernel<<<dim3(24, 32), 256>>>(x, W_attn, b_attn, kout, vout);
    // Attention: (T/64, H, B) = (32, 16, 2)
    flash_kernel<<<dim3(32, 16, 2), 256>>>(kout, vout);
    // Proj: M=4096, N=1024 -> grid (8, 32)
    proj_gemm_kernel<<<dim3(8, 32), 256>>>(W_proj, b_proj, y);
}

// round 2
// speedup vs baseline: 1.4415x; 1.4415x over previous
#include <cuda_runtime.h>
#include <math.h>
#include <stdint.h>

// Problem constants: B=2, T=2048, C=1024, H=16, hd=64
constexpr int kT  = 2048;
constexpr int kC  = 1024;
constexpr int kH  = 16;
constexpr int kHD = 64;
constexpr int kB  = 2;

// Scratch (allocation-free rule: __device__ globals)
__device__ float g_q[kB * kH * kT * kHD];     // Q in [B,H,T,hd]   (16 MB)
__device__ float g_yatt[kB * kT * kC];        // attention out, [B,T,C] (16 MB)

// ---------------------------------------------------------------------------
// TF32 helpers
// ---------------------------------------------------------------------------
__device__ __forceinline__ float to_tf32(float x) {
    float r;
    asm("cvt.rna.tf32.f32 %0, %1;" : "=f"(r) : "f"(x));
    return r;
}

__device__ __forceinline__ void mma_tf32(float* c, const uint32_t* a, const uint32_t* b) {
    asm volatile(
        "mma.sync.aligned.m16n8k8.row.col.f32.tf32.tf32.f32 "
        "{%0,%1,%2,%3}, {%4,%5,%6,%7}, {%8,%9}, {%0,%1,%2,%3};\n"
        : "+f"(c[0]), "+f"(c[1]), "+f"(c[2]), "+f"(c[3])
        : "r"(a[0]), "r"(a[1]), "r"(a[2]), "r"(a[3]), "r"(b[0]), "r"(b[1]));
}

// ---------------------------------------------------------------------------
// TF32 MMA GEMM core. CTA tile 128x128, BK=32, 256 threads (8 warps: 2m x 4n),
// warp tile 64x32 = 4x4 m16n8k8 tiles. Smem holds fragment-order data with an
// XOR swizzle so all fragment LDS are conflict-free.
//
// Smem layout:
//   AsF[kc(4)][mt(8)][j(4)][slot(32)]   slot = lane ^ ((kc*2 + (j>>1))*4)
//   BsF[kc(4)][nt(16)][j(2)][slot(32)]  slot = lane ^ ((nt&7)*4)
// Fragment semantics (m16n8k8, lane: gid=lane>>2, tig=lane&3):
//   A j=0:(gid,tig) j=1:(gid+8,tig) j=2:(gid,tig+4) j=3:(gid+8,tig+4)
//   B j=0:(tig,gid) j=1:(tig+4,gid)
// ---------------------------------------------------------------------------
template <int N_, typename Epilogue>
__device__ __forceinline__ void gemm_tf32_core(
    const float* __restrict__ A, const float* __restrict__ W,
    Epilogue epi)
{
    constexpr int K = kC;  // 1024
    __shared__ float AsF[4 * 8 * 4 * 32];    // 16 KB
    __shared__ float BsF[4 * 16 * 2 * 32];   // 16 KB

    const int m0 = blockIdx.y * 128;
    const int n0 = blockIdx.x * 128;
    const int tid  = threadIdx.x;
    const int lane = tid & 31;
    const int wid  = tid >> 5;
    const int wm = wid >> 2;      // 0..1
    const int wn = wid & 3;       // 0..3

    float acc[4][4][4];
#pragma unroll
    for (int i = 0; i < 4; i++)
#pragma unroll
        for (int j = 0; j < 4; j++)
#pragma unroll
            for (int c = 0; c < 4; c++) acc[i][j][c] = 0.f;

    for (int k0 = 0; k0 < K; k0 += 32) {
        __syncthreads();
        // ---- stage A: 128 rows x 32 k, 1024 float4, 4 per thread ----
#pragma unroll
        for (int it = 0; it < 4; it++) {
            int f = it * 256 + tid;
            int r = f >> 3;           // 0..127
            int kq = f & 7;           // float4 col index (k_local = kq*4..+3)
            float4 a4 = *reinterpret_cast<const float4*>(A + (size_t)(m0 + r) * K + k0 + kq * 4);
            int kc = kq >> 1, jc = kq & 1;
            int mt = r >> 4, rr = r & 15;
            int gid = rr & 7, jr = rr >> 3;
            int xorv = kq * 4;        // = (kc*2+jc)*4
            float* dst = &AsF[(((kc * 8 + mt) * 4) + (jr + 2 * jc)) * 32];
            dst[(gid * 4 + 0) ^ xorv] = to_tf32(a4.x);
            dst[(gid * 4 + 1) ^ xorv] = to_tf32(a4.y);
            dst[(gid * 4 + 2) ^ xorv] = to_tf32(a4.z);
            dst[(gid * 4 + 3) ^ xorv] = to_tf32(a4.w);
        }
        // ---- stage B: 32 k x 128 n, 1024 float4, 4 per thread ----
#pragma unroll
        for (int it = 0; it < 4; it++) {
            int f = it * 256 + tid;
            int kk = f >> 5;          // 0..31
            int c4 = f & 31;          // float4 col (n_local = c4*4..+3)
            float4 b4 = *reinterpret_cast<const float4*>(W + (size_t)(k0 + kk) * N_ + n0 + c4 * 4);
            int kc = kk >> 3, k7 = kk & 7;
            int tig = k7 & 3, j = k7 >> 2;
            int nt = c4 >> 1;         // n_local>>3, constant over the 4 elems
            int g0 = (c4 & 1) * 4;    // gid base
            int xorb = (nt & 7) * 4;
            float* dst = &BsF[(((kc * 16 + nt) * 2) + j) * 32];
            dst[((g0 + 0) * 4 + tig) ^ xorb] = to_tf32(b4.x);
            dst[((g0 + 1) * 4 + tig) ^ xorb] = to_tf32(b4.y);
            dst[((g0 + 2) * 4 + tig) ^ xorb] = to_tf32(b4.z);
            dst[((g0 + 3) * 4 + tig) ^ xorb] = to_tf32(b4.w);
        }
        __syncthreads();

        // ---- compute: 4 k-chunks of 8 ----
#pragma unroll
        for (int kc = 0; kc < 4; kc++) {
            uint32_t a[4][4], b[4][2];
#pragma unroll
            for (int mt = 0; mt < 4; mt++) {
                const float* ap = &AsF[((kc * 8 + wm * 4 + mt) * 4) * 32];
#pragma unroll
                for (int j = 0; j < 4; j++) {
                    int xo = (kc * 2 + (j >> 1)) * 4;
                    a[mt][j] = __float_as_uint(ap[j * 32 + (lane ^ xo)]);
                }
            }
#pragma unroll
            for (int nt = 0; nt < 4; nt++) {
                int ntg = wn * 4 + nt;
                const float* bp = &BsF[((kc * 16 + ntg) * 2) * 32];
                int xo = (ntg & 7) * 4;
                b[nt][0] = __float_as_uint(bp[(lane ^ xo)]);
                b[nt][1] = __float_as_uint(bp[32 + (lane ^ xo)]);
            }
#pragma unroll
            for (int mt = 0; mt < 4; mt++)
#pragma unroll
                for (int nt = 0; nt < 4; nt++)
                    mma_tf32(acc[mt][nt], a[mt], b[nt]);
        }
    }

    // ---- epilogue ----
    const int gid = lane >> 2, tig = lane & 3;
#pragma unroll
    for (int mt = 0; mt < 4; mt++)
#pragma unroll
        for (int nt = 0; nt < 4; nt++)
#pragma unroll
            for (int c = 0; c < 4; c++) {
                int m = m0 + wm * 64 + mt * 16 + gid + 8 * (c >> 1);
                int n = n0 + wn * 32 + nt * 8 + tig * 2 + (c & 1);
                epi(m, n, acc[mt][nt][c]);
            }
}

// ---------------------------------------------------------------------------
// QKV GEMM: x[4096,1024] @ W_attn[1024,3072] + bias; scatter epilogue
// ---------------------------------------------------------------------------
struct QkvEpilogue {
    const float* bias;
    float* kout;
    float* vout;
    __device__ __forceinline__ void operator()(int m, int n, float v) const {
        v += bias[n];
        int bidx = m >> 11;        // / 2048
        int t    = m & 2047;
        int s = n >> 10;           // 0:q 1:k 2:v
        int cc = n & 1023;
        int h = cc >> 6, d = cc & 63;
        int idx = ((bidx * kH + h) * kT + t) * kHD + d;
        if (s == 0)      g_q[idx]  = v;
        else if (s == 1) kout[idx] = v;
        else             vout[idx] = v;
    }
};

__global__ void __launch_bounds__(256, 2) qkv_gemm_kernel(
    const float* __restrict__ A, const float* __restrict__ W,
    const float* __restrict__ bias,
    float* __restrict__ kout, float* __restrict__ vout)
{
    QkvEpilogue epi{bias, kout, vout};
    gemm_tf32_core<3 * kC>(A, W, epi);
}

// ---------------------------------------------------------------------------
// Proj GEMM: g_yatt[4096,1024] @ W_proj[1024,1024] + bias -> y
// ---------------------------------------------------------------------------
struct ProjEpilogue {
    const float* bias;
    float* out;
    __device__ __forceinline__ void operator()(int m, int n, float v) const {
        out[(size_t)m * kC + n] = v + bias[n];
    }
};

__global__ void __launch_bounds__(256, 2) proj_gemm_kernel(
    const float* __restrict__ W, const float* __restrict__ bias,
    float* __restrict__ out)
{
    ProjEpilogue epi{bias, out};
    gemm_tf32_core<kC>(g_yatt, W, epi);
}

// ---------------------------------------------------------------------------
// Flash attention (fp32, causal). One CTA per (q-tile of 64, head, batch).
// BR=64, BC=32. 256 threads: 16 row-groups x 16 col-groups. (unchanged)
// ---------------------------------------------------------------------------
__global__ void __launch_bounds__(256) flash_kernel(
    const float* __restrict__ Kg, const float* __restrict__ Vg)
{
    __shared__ float Qs[64][68];
    __shared__ float Ks[64][33];   // transposed [d][c]
    __shared__ float Vs[32][64];
    __shared__ float Ss[64][33];
    __shared__ float m_s[64], l_s[64], alpha_s[64];

    const int tid = threadIdx.x;
    const int qi = blockIdx.x, h = blockIdx.y, b = blockIdx.z;
    const int qbase = qi * 64;
    const size_t head_off = (size_t)(b * kH + h) * kT * kHD;
    const float* Qp = g_q + head_off;
    const float* Kp = Kg + head_off;
    const float* Vp = Vg + head_off;

#pragma unroll
    for (int it = 0; it < 4; it++) {
        int idx = tid + it * 256;
        int r = idx >> 4;
        int dp = (idx & 15) * 4;
        float4 q4 = *reinterpret_cast<const float4*>(Qp + (size_t)(qbase + r) * kHD + dp);
        Qs[r][dp + 0] = q4.x; Qs[r][dp + 1] = q4.y;
        Qs[r][dp + 2] = q4.z; Qs[r][dp + 3] = q4.w;
    }
    if (tid < 64) { m_s[tid] = -INFINITY; l_s[tid] = 0.f; }

    const int rg = tid >> 4;
    const int cg = tid & 15;
    const int r0 = rg * 4;
    const int sc0 = cg * 2;
    const int d0 = cg * 4;

    float O[4][4];
#pragma unroll
    for (int i = 0; i < 4; i++)
#pragma unroll
        for (int j = 0; j < 4; j++) O[i][j] = 0.f;

    const float scale = 0.125f;
    const int ntiles = 2 * qi + 2;

    for (int jt = 0; jt < ntiles; jt++) {
        __syncthreads();
#pragma unroll
        for (int it = 0; it < 2; it++) {
            int idx = tid + it * 256;
            int c = idx >> 4;
            int dp = (idx & 15) * 4;
            float4 k4 = *reinterpret_cast<const float4*>(Kp + (size_t)(jt * 32 + c) * kHD + dp);
            Ks[dp + 0][c] = k4.x; Ks[dp + 1][c] = k4.y;
            Ks[dp + 2][c] = k4.z; Ks[dp + 3][c] = k4.w;
            float4 v4 = *reinterpret_cast<const float4*>(Vp + (size_t)(jt * 32 + c) * kHD + dp);
            *reinterpret_cast<float4*>(&Vs[c][dp]) = v4;
        }
        __syncthreads();

        float s00 = 0.f, s01 = 0.f, s10 = 0.f, s11 = 0.f;
        float s20 = 0.f, s21 = 0.f, s30 = 0.f, s31 = 0.f;
#pragma unroll
        for (int d = 0; d < 64; d++) {
            float kv0 = Ks[d][sc0], kv1 = Ks[d][sc0 + 1];
            float q0 = Qs[r0 + 0][d], q1 = Qs[r0 + 1][d];
            float q2 = Qs[r0 + 2][d], q3 = Qs[r0 + 3][d];
            s00 = fmaf(q0, kv0, s00); s01 = fmaf(q0, kv1, s01);
            s10 = fmaf(q1, kv0, s10); s11 = fmaf(q1, kv1, s11);
            s20 = fmaf(q2, kv0, s20); s21 = fmaf(q2, kv1, s21);
            s30 = fmaf(q3, kv0, s30); s31 = fmaf(q3, kv1, s31);
        }
        {
            float sv[4][2] = {{s00, s01}, {s10, s11}, {s20, s21}, {s30, s31}};
            const bool maskTile = (jt * 32 + 31 > qbase);
#pragma unroll
            for (int i = 0; i < 4; i++)
#pragma unroll
                for (int jj = 0; jj < 2; jj++) {
                    float val = sv[i][jj] * scale;
                    if (maskTile && (jt * 32 + sc0 + jj > qbase + r0 + i)) val = -INFINITY;
                    Ss[r0 + i][sc0 + jj] = val;
                }
        }
        __syncthreads();

        if (tid < 64) {
            int r = tid;
            float mo = m_s[r];
            float mx = mo;
#pragma unroll
            for (int c = 0; c < 32; c++) mx = fmaxf(mx, Ss[r][c]);
            float alpha = __expf(mo - mx);
            float sum = 0.f;
#pragma unroll
            for (int c = 0; c < 32; c++) {
                float p = __expf(Ss[r][c] - mx);
                Ss[r][c] = p;
                sum += p;
            }
            l_s[r] = l_s[r] * alpha + sum;
            m_s[r] = mx;
            alpha_s[r] = alpha;
        }
        __syncthreads();

#pragma unroll
        for (int i = 0; i < 4; i++) {
            float a = alpha_s[r0 + i];
#pragma unroll
            for (int jj = 0; jj < 4; jj++) O[i][jj] *= a;
        }
#pragma unroll
        for (int k = 0; k < 32; k++) {
            float4 v4 = *reinterpret_cast<float4*>(&Vs[k][d0]);
            float p0 = Ss[r0 + 0][k], p1 = Ss[r0 + 1][k];
            float p2 = Ss[r0 + 2][k], p3 = Ss[r0 + 3][k];
            O[0][0] = fmaf(p0, v4.x, O[0][0]); O[0][1] = fmaf(p0, v4.y, O[0][1]);
            O[0][2] = fmaf(p0, v4.z, O[0][2]); O[0][3] = fmaf(p0, v4.w, O[0][3]);
            O[1][0] = fmaf(p1, v4.x, O[1][0]); O[1][1] = fmaf(p1, v4.y, O[1][1]);
            O[1][2] = fmaf(p1, v4.z, O[1][2]); O[1][3] = fmaf(p1, v4.w, O[1][3]);
            O[2][0] = fmaf(p2, v4.x, O[2][0]); O[2][1] = fmaf(p2, v4.y, O[2][1]);
            O[2][2] = fmaf(p2, v4.z, O[2][2]); O[2][3] = fmaf(p2, v4.w, O[2][3]);
            O[3][0] = fmaf(p3, v4.x, O[3][0]); O[3][1] = fmaf(p3, v4.y, O[3][1]);
            O[3][2] = fmaf(p3, v4.z, O[3][2]); O[3][3] = fmaf(p3, v4.w, O[3][3]);
        }
    }
    __syncthreads();

#pragma unroll
    for (int i = 0; i < 4; i++) {
        float inv = 1.f / l_s[r0 + i];
        int t = qbase + r0 + i;
        float* yp = g_yatt + (size_t)(b * kT + t) * kC + h * kHD + d0;
        yp[0] = O[i][0] * inv;
        yp[1] = O[i][1] * inv;
        yp[2] = O[i][2] * inv;
        yp[3] = O[i][3] * inv;
    }
}

// ---------------------------------------------------------------------------
// Launch: qkv -> flash -> proj, sequential on default stream (capturable).
// Output layout: [ y (B*T*C) | k (B*H*T*hd) | v (B*H*T*hd) ]
// ---------------------------------------------------------------------------
extern "C" void kernel_launch(void* const* d_in, const int* in_sizes, int n_in,
                              void* d_out, int out_size)
{
    const float* x      = (const float*)d_in[0];
    const float* W_attn = (const float*)d_in[1];
    const float* b_attn = (const float*)d_in[2];
    const float* W_proj = (const float*)d_in[3];
    const float* b_proj = (const float*)d_in[4];

    float* y = (float*)d_out;
    const int seg = out_size / 3;       // 4,194,304 each
    float* kout = y + seg;
    float* vout = y + 2 * seg;

    qkv_gemm_kernel<<<dim3(24, 32), 256>>>(x, W_attn, b_attn, kout, vout);
    flash_kernel<<<dim3(32, 16, 2), 256>>>(kout, vout);
    proj_gemm_kernel<<<dim3(8, 32), 256>>>(W_proj, b_proj, y);
}

// round 3
// speedup vs baseline: 2.6114x; 1.8116x over previous
#include <cuda_runtime.h>
#include <math.h>
#include <stdint.h>

// Problem constants: B=2, T=2048, C=1024, H=16, hd=64
constexpr int kT  = 2048;
constexpr int kC  = 1024;
constexpr int kH  = 16;
constexpr int kHD = 64;
constexpr int kB  = 2;

// Scratch (allocation-free rule: __device__ globals)
__device__ float g_q[kB * kH * kT * kHD];     // Q in [B,H,T,hd]   (16 MB)
__device__ float g_yatt[kB * kT * kC];        // attention out, [B,T,C] (16 MB)

// ---------------------------------------------------------------------------
// TF32 helpers
// ---------------------------------------------------------------------------
__device__ __forceinline__ float to_tf32(float x) {
    float r;
    asm("cvt.rna.tf32.f32 %0, %1;" : "=f"(r) : "f"(x));
    return r;
}

__device__ __forceinline__ void mma_tf32(float* c, const uint32_t* a, const uint32_t* b) {
    asm volatile(
        "mma.sync.aligned.m16n8k8.row.col.f32.tf32.tf32.f32 "
        "{%0,%1,%2,%3}, {%4,%5,%6,%7}, {%8,%9}, {%0,%1,%2,%3};\n"
        : "+f"(c[0]), "+f"(c[1]), "+f"(c[2]), "+f"(c[3])
        : "r"(a[0]), "r"(a[1]), "r"(a[2]), "r"(a[3]), "r"(b[0]), "r"(b[1]));
}

// ---------------------------------------------------------------------------
// TF32 MMA GEMM core (unchanged from R2). CTA 128x128, BK=32, 256 thr.
// ---------------------------------------------------------------------------
template <int N_, typename Epilogue>
__device__ __forceinline__ void gemm_tf32_core(
    const float* __restrict__ A, const float* __restrict__ W,
    Epilogue epi)
{
    constexpr int K = kC;  // 1024
    __shared__ float AsF[4 * 8 * 4 * 32];    // 16 KB
    __shared__ float BsF[4 * 16 * 2 * 32];   // 16 KB

    const int m0 = blockIdx.y * 128;
    const int n0 = blockIdx.x * 128;
    const int tid  = threadIdx.x;
    const int lane = tid & 31;
    const int wid  = tid >> 5;
    const int wm = wid >> 2;
    const int wn = wid & 3;

    float acc[4][4][4];
#pragma unroll
    for (int i = 0; i < 4; i++)
#pragma unroll
        for (int j = 0; j < 4; j++)
#pragma unroll
            for (int c = 0; c < 4; c++) acc[i][j][c] = 0.f;

    for (int k0 = 0; k0 < K; k0 += 32) {
        __syncthreads();
#pragma unroll
        for (int it = 0; it < 4; it++) {
            int f = it * 256 + tid;
            int r = f >> 3;
            int kq = f & 7;
            float4 a4 = *reinterpret_cast<const float4*>(A + (size_t)(m0 + r) * K + k0 + kq * 4);
            int kc = kq >> 1, jc = kq & 1;
            int mt = r >> 4, rr = r & 15;
            int gid = rr & 7, jr = rr >> 3;
            int xorv = kq * 4;
            float* dst = &AsF[(((kc * 8 + mt) * 4) + (jr + 2 * jc)) * 32];
            dst[(gid * 4 + 0) ^ xorv] = to_tf32(a4.x);
            dst[(gid * 4 + 1) ^ xorv] = to_tf32(a4.y);
            dst[(gid * 4 + 2) ^ xorv] = to_tf32(a4.z);
            dst[(gid * 4 + 3) ^ xorv] = to_tf32(a4.w);
        }
#pragma unroll
        for (int it = 0; it < 4; it++) {
            int f = it * 256 + tid;
            int kk = f >> 5;
            int c4 = f & 31;
            float4 b4 = *reinterpret_cast<const float4*>(W + (size_t)(k0 + kk) * N_ + n0 + c4 * 4);
            int kc = kk >> 3, k7 = kk & 7;
            int tig = k7 & 3, j = k7 >> 2;
            int nt = c4 >> 1;
            int g0 = (c4 & 1) * 4;
            int xorb = (nt & 7) * 4;
            float* dst = &BsF[(((kc * 16 + nt) * 2) + j) * 32];
            dst[((g0 + 0) * 4 + tig) ^ xorb] = to_tf32(b4.x);
            dst[((g0 + 1) * 4 + tig) ^ xorb] = to_tf32(b4.y);
            dst[((g0 + 2) * 4 + tig) ^ xorb] = to_tf32(b4.z);
            dst[((g0 + 3) * 4 + tig) ^ xorb] = to_tf32(b4.w);
        }
        __syncthreads();

#pragma unroll
        for (int kc = 0; kc < 4; kc++) {
            uint32_t a[4][4], b[4][2];
#pragma unroll
            for (int mt = 0; mt < 4; mt++) {
                const float* ap = &AsF[((kc * 8 + wm * 4 + mt) * 4) * 32];
#pragma unroll
                for (int j = 0; j < 4; j++) {
                    int xo = (kc * 2 + (j >> 1)) * 4;
                    a[mt][j] = __float_as_uint(ap[j * 32 + (lane ^ xo)]);
                }
            }
#pragma unroll
            for (int nt = 0; nt < 4; nt++) {
                int ntg = wn * 4 + nt;
                const float* bp = &BsF[((kc * 16 + ntg) * 2) * 32];
                int xo = (ntg & 7) * 4;
                b[nt][0] = __float_as_uint(bp[(lane ^ xo)]);
                b[nt][1] = __float_as_uint(bp[32 + (lane ^ xo)]);
            }
#pragma unroll
            for (int mt = 0; mt < 4; mt++)
#pragma unroll
                for (int nt = 0; nt < 4; nt++)
                    mma_tf32(acc[mt][nt], a[mt], b[nt]);
        }
    }

    const int gid = lane >> 2, tig = lane & 3;
#pragma unroll
    for (int mt = 0; mt < 4; mt++)
#pragma unroll
        for (int nt = 0; nt < 4; nt++)
#pragma unroll
            for (int c = 0; c < 4; c++) {
                int m = m0 + wm * 64 + mt * 16 + gid + 8 * (c >> 1);
                int n = n0 + wn * 32 + nt * 8 + tig * 2 + (c & 1);
                epi(m, n, acc[mt][nt][c]);
            }
}

struct QkvEpilogue {
    const float* bias;
    float* kout;
    float* vout;
    __device__ __forceinline__ void operator()(int m, int n, float v) const {
        v += bias[n];
        int bidx = m >> 11;
        int t    = m & 2047;
        int s = n >> 10;
        int cc = n & 1023;
        int h = cc >> 6, d = cc & 63;
        int idx = ((bidx * kH + h) * kT + t) * kHD + d;
        if (s == 0)      g_q[idx]  = v;
        else if (s == 1) kout[idx] = v;
        else             vout[idx] = v;
    }
};

__global__ void __launch_bounds__(256, 2) qkv_gemm_kernel(
    const float* __restrict__ A, const float* __restrict__ W,
    const float* __restrict__ bias,
    float* __restrict__ kout, float* __restrict__ vout)
{
    QkvEpilogue epi{bias, kout, vout};
    gemm_tf32_core<3 * kC>(A, W, epi);
}

struct ProjEpilogue {
    const float* bias;
    float* out;
    __device__ __forceinline__ void operator()(int m, int n, float v) const {
        out[(size_t)m * kC + n] = v + bias[n];
    }
};

__global__ void __launch_bounds__(256, 2) proj_gemm_kernel(
    const float* __restrict__ W, const float* __restrict__ bias,
    float* __restrict__ out)
{
    ProjEpilogue epi{bias, out};
    gemm_tf32_core<kC>(g_yatt, W, epi);
}

// ---------------------------------------------------------------------------
// TF32 MMA flash attention. BR=BC=64. 128 threads = 4 warps; warp w owns
// q-rows [w*16, w*16+16) x all 64 cols => softmax is warp-local.
// Smem (dynamic, 52224 B): Ks[64][68] row-major, Vt[64][68] transposed,
// Ss[64][68] P round-trip (per-warp-private rows).
// Fragment bank math (stride 68 == 4 mod 32): read bank = 4*gid+tig = lane
// => all fragment LDS conflict-free.
// ---------------------------------------------------------------------------
constexpr int kFlashSmemBytes = 3 * 64 * 68 * 4;

__global__ void __launch_bounds__(128) flash_kernel(
    const float* __restrict__ Kg, const float* __restrict__ Vg)
{
    extern __shared__ float sm[];
    float* Ks = sm;               // [64][68]
    float* Vt = sm + 64 * 68;     // [64][68]  (Vt[d][c])
    float* Ss = sm + 2 * 64 * 68; // [64][68]

    const int tid  = threadIdx.x;
    const int lane = tid & 31;
    const int wid  = tid >> 5;
    const int gid  = lane >> 2;
    const int tig  = lane & 3;
    const int qi = blockIdx.x, h = blockIdx.y, b = blockIdx.z;
    const int qbase = qi * 64;
    const int r0 = wid * 16;

    const size_t head_off = (size_t)(b * kH + h) * kT * kHD;
    const float* Qp = g_q + head_off;
    const float* Kp = Kg + head_off;
    const float* Vp = Vg + head_off;

    // ---- stage Q tile (64x64) into Ss, then load fragments (scaled, tf32) ----
#pragma unroll
    for (int it = 0; it < 8; it++) {
        int f = it * 128 + tid;
        int r = f >> 4, dq = (f & 15) * 4;
        float4 q4 = *reinterpret_cast<const float4*>(Qp + (size_t)(qbase + r) * kHD + dq);
        float* d = Ss + r * 68 + dq;
        d[0] = q4.x; d[1] = q4.y; d[2] = q4.z; d[3] = q4.w;
    }
    __syncthreads();

    uint32_t qf[8][4];
#pragma unroll
    for (int kc = 0; kc < 8; kc++) {
        const float* base = Ss + (r0 + gid) * 68 + kc * 8 + tig;
        qf[kc][0] = __float_as_uint(to_tf32(0.125f * base[0]));
        qf[kc][1] = __float_as_uint(to_tf32(0.125f * base[8 * 68]));
        qf[kc][2] = __float_as_uint(to_tf32(0.125f * base[4]));
        qf[kc][3] = __float_as_uint(to_tf32(0.125f * base[8 * 68 + 4]));
    }

    float mA = -INFINITY, mB = -INFINITY, lA = 0.f, lB = 0.f;
    float oacc[8][4];
#pragma unroll
    for (int nt = 0; nt < 8; nt++)
#pragma unroll
        for (int c = 0; c < 4; c++) oacc[nt][c] = 0.f;

    const int ntiles = qi + 1;
    const int vdpb = tid & 15, vcb4 = tid >> 4;   // V transpose block coords

    for (int jt = 0; jt < ntiles; jt++) {
        __syncthreads();   // previous iteration's Ks/Vt readers are done

        // ---- stage K tile row-major (tf32) ----
#pragma unroll
        for (int it = 0; it < 8; it++) {
            int f = it * 128 + tid;
            int r = f >> 4, dq = (f & 15) * 4;
            float4 k4 = *reinterpret_cast<const float4*>(Kp + (size_t)(jt * 64 + r) * kHD + dq);
            float* d = Ks + r * 68 + dq;
            d[0] = to_tf32(k4.x); d[1] = to_tf32(k4.y);
            d[2] = to_tf32(k4.z); d[3] = to_tf32(k4.w);
        }
        // ---- stage V transposed via 4x4 in-register blocks (tf32) ----
#pragma unroll
        for (int it = 0; it < 2; it++) {
            int cb = vcb4 + 8 * it;               // key block 0..15
            const float* vsrc = Vp + (size_t)(jt * 64 + cb * 4) * kHD + vdpb * 4;
            float4 a0 = *reinterpret_cast<const float4*>(vsrc);
            float4 a1 = *reinterpret_cast<const float4*>(vsrc + kHD);
            float4 a2 = *reinterpret_cast<const float4*>(vsrc + 2 * kHD);
            float4 a3 = *reinterpret_cast<const float4*>(vsrc + 3 * kHD);
            float4 t0 = {to_tf32(a0.x), to_tf32(a1.x), to_tf32(a2.x), to_tf32(a3.x)};
            float4 t1 = {to_tf32(a0.y), to_tf32(a1.y), to_tf32(a2.y), to_tf32(a3.y)};
            float4 t2 = {to_tf32(a0.z), to_tf32(a1.z), to_tf32(a2.z), to_tf32(a3.z)};
            float4 t3 = {to_tf32(a0.w), to_tf32(a1.w), to_tf32(a2.w), to_tf32(a3.w)};
            *reinterpret_cast<float4*>(Vt + (vdpb * 4 + 0) * 68 + cb * 4) = t0;
            *reinterpret_cast<float4*>(Vt + (vdpb * 4 + 1) * 68 + cb * 4) = t1;
            *reinterpret_cast<float4*>(Vt + (vdpb * 4 + 2) * 68 + cb * 4) = t2;
            *reinterpret_cast<float4*>(Vt + (vdpb * 4 + 3) * 68 + cb * 4) = t3;
        }
        __syncthreads();

        // ---- S = (Q/8) K^T : 8 n-tiles x 8 k-chunks of m16n8k8 ----
        float sa[8][4];
#pragma unroll
        for (int nt = 0; nt < 8; nt++)
#pragma unroll
            for (int c = 0; c < 4; c++) sa[nt][c] = 0.f;
#pragma unroll
        for (int kc = 0; kc < 8; kc++) {
#pragma unroll
            for (int nt = 0; nt < 8; nt++) {
                const float* bp = Ks + (nt * 8 + gid) * 68 + kc * 8 + tig;
                uint32_t bb[2];
                bb[0] = __float_as_uint(bp[0]);
                bb[1] = __float_as_uint(bp[4]);
                mma_tf32(sa[nt], qf[kc], bb);
            }
        }

        // ---- causal mask on diagonal tile ----
        if (jt == qi) {
            int rowA = r0 + gid, rowB = rowA + 8;
#pragma unroll
            for (int nt = 0; nt < 8; nt++) {
                int c0 = nt * 8 + tig * 2, c1 = c0 + 1;
                if (c0 > rowA) sa[nt][0] = -INFINITY;
                if (c1 > rowA) sa[nt][1] = -INFINITY;
                if (c0 > rowB) sa[nt][2] = -INFINITY;
                if (c1 > rowB) sa[nt][3] = -INFINITY;
            }
        }

        // ---- warp-local online softmax ----
        float mxA = -INFINITY, mxB = -INFINITY;
#pragma unroll
        for (int nt = 0; nt < 8; nt++) {
            mxA = fmaxf(mxA, fmaxf(sa[nt][0], sa[nt][1]));
            mxB = fmaxf(mxB, fmaxf(sa[nt][2], sa[nt][3]));
        }
        mxA = fmaxf(mxA, __shfl_xor_sync(0xffffffff, mxA, 1));
        mxA = fmaxf(mxA, __shfl_xor_sync(0xffffffff, mxA, 2));
        mxB = fmaxf(mxB, __shfl_xor_sync(0xffffffff, mxB, 1));
        mxB = fmaxf(mxB, __shfl_xor_sync(0xffffffff, mxB, 2));

        float mnA = fmaxf(mA, mxA), mnB = fmaxf(mB, mxB);
        float alphaA = __expf(mA - mnA), alphaB = __expf(mB - mnB);

        float sumA = 0.f, sumB = 0.f;
        float* prowA = Ss + (r0 + gid) * 68 + tig * 2;
        float* prowB = prowA + 8 * 68;
#pragma unroll
        for (int nt = 0; nt < 8; nt++) {
            float p0 = __expf(sa[nt][0] - mnA);
            float p1 = __expf(sa[nt][1] - mnA);
            float p2 = __expf(sa[nt][2] - mnB);
            float p3 = __expf(sa[nt][3] - mnB);
            float q0 = to_tf32(p0), q1 = to_tf32(p1);
            float q2 = to_tf32(p2), q3 = to_tf32(p3);
            sumA += q0 + q1;     // sum what we actually store -> unbiased P/l
            sumB += q2 + q3;
            prowA[nt * 8 + 0] = q0; prowA[nt * 8 + 1] = q1;
            prowB[nt * 8 + 0] = q2; prowB[nt * 8 + 1] = q3;
        }
        sumA += __shfl_xor_sync(0xffffffff, sumA, 1);
        sumA += __shfl_xor_sync(0xffffffff, sumA, 2);
        sumB += __shfl_xor_sync(0xffffffff, sumB, 1);
        sumB += __shfl_xor_sync(0xffffffff, sumB, 2);

        lA = lA * alphaA + sumA;  mA = mnA;
        lB = lB * alphaB + sumB;  mB = mnB;

#pragma unroll
        for (int nt = 0; nt < 8; nt++) {
            oacc[nt][0] *= alphaA; oacc[nt][1] *= alphaA;
            oacc[nt][2] *= alphaB; oacc[nt][3] *= alphaB;
        }
        __syncwarp();

        // ---- O += P V : A-frags from Ss (own rows), B-frags from Vt ----
#pragma unroll
        for (int kc = 0; kc < 8; kc++) {
            const float* ap = Ss + (r0 + gid) * 68 + kc * 8 + tig;
            uint32_t pa[4];
            pa[0] = __float_as_uint(ap[0]);
            pa[1] = __float_as_uint(ap[8 * 68]);
            pa[2] = __float_as_uint(ap[4]);
            pa[3] = __float_as_uint(ap[8 * 68 + 4]);
#pragma unroll
            for (int nt = 0; nt < 8; nt++) {
                const float* bp = Vt + (nt * 8 + gid) * 68 + kc * 8 + tig;
                uint32_t bb[2];
                bb[0] = __float_as_uint(bp[0]);
                bb[1] = __float_as_uint(bp[4]);
                mma_tf32(oacc[nt], pa, bb);
            }
        }
        __syncwarp();   // keep Ss reads ahead of next iteration's P stores
    }

    // ---- normalize + store to g_yatt [B,T,C] (head h at cols h*64..) ----
    float ilA = 1.f / lA, ilB = 1.f / lB;
    float* ypA = g_yatt + ((size_t)(b * kT + qbase + r0 + gid)) * kC + h * kHD;
    float* ypB = ypA + (size_t)8 * kC;
#pragma unroll
    for (int nt = 0; nt < 8; nt++) {
        float2 vA = {oacc[nt][0] * ilA, oacc[nt][1] * ilA};
        float2 vB = {oacc[nt][2] * ilB, oacc[nt][3] * ilB};
        *reinterpret_cast<float2*>(ypA + nt * 8 + tig * 2) = vA;
        *reinterpret_cast<float2*>(ypB + nt * 8 + tig * 2) = vB;
    }
}

// ---------------------------------------------------------------------------
// Launch: qkv -> flash -> proj, sequential on default stream (capturable).
// Output layout: [ y (B*T*C) | k (B*H*T*hd) | v (B*H*T*hd) ]
// ---------------------------------------------------------------------------
extern "C" void kernel_launch(void* const* d_in, const int* in_sizes, int n_in,
                              void* d_out, int out_size)
{
    const float* x      = (const float*)d_in[0];
    const float* W_attn = (const float*)d_in[1];
    const float* b_attn = (const float*)d_in[2];
    const float* W_proj = (const float*)d_in[3];
    const float* b_proj = (const float*)d_in[4];

    float* y = (float*)d_out;
    const int seg = out_size / 3;       // 4,194,304 each
    float* kout = y + seg;
    float* vout = y + 2 * seg;

    cudaFuncSetAttribute(flash_kernel,
                         cudaFuncAttributeMaxDynamicSharedMemorySize,
                         kFlashSmemBytes);

    qkv_gemm_kernel<<<dim3(24, 32), 256>>>(x, W_attn, b_attn, kout, vout);
    flash_kernel<<<dim3(32, 16, 2), 128, kFlashSmemBytes>>>(kout, vout);
    proj_gemm_kernel<<<dim3(8, 32), 256>>>(W_proj, b_proj, y);
}